// round 4
// baseline (speedup 1.0000x reference)
#include <cuda_runtime.h>
#include <cstddef>

#define NH 50000
#define NF 200000
#define HDIM 128
#define NUM_BLOCKS 2

// ---------------- scratch (device globals; no allocations allowed) ----------------
__device__ float g_agg_f0[(size_t)NF * HDIM];   // sends aggregation  (dst=flow)
__device__ float g_agg_f1[(size_t)NF * HDIM];   // precedes aggregation (dst=flow)
__device__ float g_agg_h0[(size_t)NH * HDIM];   // rev_sends aggregation (dst=host)
__device__ float g_agg_h1[(size_t)NH * HDIM];   // reaches aggregation (dst=host)
__device__ float g_f_buf1[(size_t)NF * HDIM];
__device__ float g_f_buf2[(size_t)NF * HDIM];
__device__ float g_h_buf1[(size_t)NH * HDIM];
__device__ float g_h_buf2[(size_t)NH * HDIM];
__device__ float g_inv_sends[NF];
__device__ float g_inv_prec[NF];
__device__ float g_inv_rev[NH];
__device__ float g_inv_reach[NH];
__device__ float g_Beff[2 * 2 * 384 * HDIM];    // [blk][type(f=0,h=1)][k=384][o=128]
__device__ float g_bias[2 * 2 * HDIM];
__device__ float g_stats[4 * HDIM];             // hsum, hsq, fsum, fsq

// ---------------- kernels ----------------

__global__ void count_deg(const int* __restrict__ ei, int E, float* __restrict__ cnt) {
    int e = blockIdx.x * blockDim.x + threadIdx.x;
    if (e < E) atomicAdd(&cnt[ei[E + e]], 1.0f);
}

__global__ void invert_cnt(float* __restrict__ c, int n) {
    int i = blockIdx.x * blockDim.x + threadIdx.x;
    if (i < n) c[i] = 1.0f / fmaxf(c[i], 1.0f);
}

// Each warp handles one edge; lane l moves 4 consecutive floats via vector red.
__global__ void scatter_add(const float* __restrict__ src, const int* __restrict__ ei,
                            int E, float* __restrict__ agg) {
    int lane = threadIdx.x & 31;
    int e = (blockIdx.x * blockDim.x + threadIdx.x) >> 5;
    if (e >= E) return;
    int s = ei[e];
    int d = ei[E + e];
    float4 v = *(const float4*)(src + (size_t)s * HDIM + lane * 4);
    float* drow = agg + (size_t)d * HDIM + lane * 4;
    asm volatile("red.global.add.v4.f32 [%0], {%1,%2,%3,%4};"
                 :: "l"(drow), "f"(v.x), "f"(v.y), "f"(v.z), "f"(v.w) : "memory");
}

// Build fused B matrices (pre-transposed, 0.5-scaled, Wr pair pre-summed) + biases.
__global__ void prep_weights(const float* __restrict__ Wl, const float* __restrict__ bl,
                             const float* __restrict__ Wr,
                             float* __restrict__ Beff, float* __restrict__ bias) {
    int i = blockIdx.x * blockDim.x + threadIdx.x;
    if (i < 2 * 2 * 384 * HDIM) {
        int o = i & 127;
        int k = (i >> 7) % 384;
        int t = ((i >> 7) / 384) & 1;
        int b = i / (2 * 384 * HDIM);
        int ta = t ? 1 : 0, tb = t ? 3 : 2;
        int seg = k >> 7, kk = k & 127;
        float v;
        if (seg == 0)      v = Wl[(((size_t)b * 4 + ta) * 128 + o) * 128 + kk];
        else if (seg == 1) v = Wl[(((size_t)b * 4 + tb) * 128 + o) * 128 + kk];
        else               v = Wr[(((size_t)b * 4 + ta) * 128 + o) * 128 + kk]
                             + Wr[(((size_t)b * 4 + tb) * 128 + o) * 128 + kk];
        Beff[i] = 0.5f * v;
    }
    if (i < 2 * 2 * HDIM) {
        int o = i & 127;
        int t = (i >> 7) & 1;
        int b = i >> 8;
        int ta = t ? 1 : 0, tb = t ? 3 : 2;
        bias[i] = 0.5f * (bl[(b * 4 + ta) * 128 + o] + bl[(b * 4 + tb) * 128 + o]);
    }
}

// Fused K=384 SGEMM: out[r][o] = sum_k Aeff[r][k]*Beff[k][o] + bias[o]
// Aeff segments: agg0*inv0 | agg1*inv1 | x_dst. BM=128, BN=128, BK=16, 8x8 microtile.
__global__ __launch_bounds__(256) void fused_gemm(
    const float* __restrict__ A0, const float* __restrict__ inv0,
    const float* __restrict__ A1, const float* __restrict__ inv1,
    const float* __restrict__ A2,
    const float* __restrict__ B, const float* __restrict__ bias,
    float* __restrict__ out, int nrows)
{
    __shared__ float As[16][128];
    __shared__ float Bs[16][128];
    int tid = threadIdx.x;
    int row0 = blockIdx.x * 128;
    int tx = tid & 15, ty = tid >> 4;
    float acc[8][8];
#pragma unroll
    for (int m = 0; m < 8; m++)
#pragma unroll
        for (int n = 0; n < 8; n++) acc[m][n] = 0.0f;

    for (int kt = 0; kt < 24; kt++) {
        int seg = kt >> 3;
        int kbase = (kt & 7) * 16;
        const float* Asrc = (seg == 0) ? A0 : (seg == 1) ? A1 : A2;
        const float* inv  = (seg == 0) ? inv0 : (seg == 1) ? inv1 : (const float*)0;
        // A tile: 128 rows x 16 cols = 512 float4, 2 per thread
#pragma unroll
        for (int i = 0; i < 2; i++) {
            int idx = tid + i * 256;
            int r  = idx >> 2;
            int c4 = idx & 3;
            int gr = row0 + r;
            float4 v = make_float4(0.f, 0.f, 0.f, 0.f);
            if (gr < nrows) {
                v = *(const float4*)(Asrc + (size_t)gr * HDIM + kbase + c4 * 4);
                if (inv) {
                    float iv = inv[gr];
                    v.x *= iv; v.y *= iv; v.z *= iv; v.w *= iv;
                }
            }
            As[c4 * 4 + 0][r] = v.x;
            As[c4 * 4 + 1][r] = v.y;
            As[c4 * 4 + 2][r] = v.z;
            As[c4 * 4 + 3][r] = v.w;
        }
        // B tile: 16 rows x 128 cols
#pragma unroll
        for (int i = 0; i < 2; i++) {
            int idx = tid + i * 256;
            int kk = idx >> 5;
            int o4 = idx & 31;
            *(float4*)&Bs[kk][o4 * 4] =
                *(const float4*)(B + (size_t)(kt * 16 + kk) * 128 + o4 * 4);
        }
        __syncthreads();
#pragma unroll
        for (int k = 0; k < 16; k++) {
            float a[8], bb[8];
#pragma unroll
            for (int m = 0; m < 8; m++) a[m] = As[k][ty * 8 + m];
#pragma unroll
            for (int n = 0; n < 8; n++) bb[n] = Bs[k][tx * 8 + n];
#pragma unroll
            for (int m = 0; m < 8; m++)
#pragma unroll
                for (int n = 0; n < 8; n++) acc[m][n] += a[m] * bb[n];
        }
        __syncthreads();
    }
#pragma unroll
    for (int m = 0; m < 8; m++) {
        int gr = row0 + ty * 8 + m;
        if (gr >= nrows) break;
#pragma unroll
        for (int n = 0; n < 8; n += 4) {
            int o = tx * 8 + n;
            float4 v;
            v.x = acc[m][n + 0] + bias[o + 0];
            v.y = acc[m][n + 1] + bias[o + 1];
            v.z = acc[m][n + 2] + bias[o + 2];
            v.w = acc[m][n + 3] + bias[o + 3];
            *(float4*)(out + (size_t)gr * HDIM + o) = v;
        }
    }
}

__global__ void bn_stats(const float* __restrict__ v, int n,
                         float* __restrict__ sum, float* __restrict__ sq) {
    int c = threadIdx.x & 127;
    int sub = threadIdx.x >> 7;  // 0..1
    float s = 0.f, s2 = 0.f;
    for (int r = blockIdx.x * 2 + sub; r < n; r += gridDim.x * 2) {
        float x = v[(size_t)r * HDIM + c];
        s += x;
        s2 += x * x;
    }
    __shared__ float sh[256], sh2[256];
    sh[threadIdx.x] = s;
    sh2[threadIdx.x] = s2;
    __syncthreads();
    if (sub == 0) {
        atomicAdd(&sum[c], sh[c] + sh[c + 128]);
        atomicAdd(&sq[c], sh2[c] + sh2[c + 128]);
    }
}

__global__ void bn_apply(const float* __restrict__ in, float* __restrict__ out, int n,
                         const float* __restrict__ sum, const float* __restrict__ sq,
                         const float* __restrict__ gamma, const float* __restrict__ beta) {
    size_t i = (size_t)blockIdx.x * blockDim.x + threadIdx.x;
    size_t total = (size_t)n * HDIM;
    if (i >= total) return;
    int c = (int)(i & 127);
    float N = (float)n;
    float mu = sum[c] / N;
    float var = sq[c] / N - mu * mu;
    float rstd = rsqrtf(var + 1e-5f);
    float x = (in[i] - mu) * rstd * gamma[c] + beta[c];
    out[i] = x >= 0.f ? x : 0.01f * x;
}

// ---------------- host ----------------
static inline void* sym(const void* s) {
    void* p = 0;
    cudaGetSymbolAddress(&p, s);
    return p;
}

extern "C" void kernel_launch(void* const* d_in, const int* in_sizes, int n_in,
                              void* d_out, int out_size) {
    const float* x_host = (const float*)d_in[0];
    const float* x_flow = (const float*)d_in[1];
    const int* ei_sends = (const int*)d_in[2];
    const int* ei_rev   = (const int*)d_in[3];
    const int* ei_prec  = (const int*)d_in[4];
    const int* ei_reach = (const int*)d_in[5];
    const float* W_l = (const float*)d_in[6];
    const float* b_l = (const float*)d_in[7];
    const float* W_r = (const float*)d_in[8];
    const float* bn_gamma = (const float*)d_in[9];
    const float* bn_beta  = (const float*)d_in[10];
    float* out = (float*)d_out;

    int E_sends = in_sizes[2] / 2;
    int E_rev   = in_sizes[3] / 2;
    int E_prec  = in_sizes[4] / 2;
    int E_reach = in_sizes[5] / 2;

    float* agg_f0 = (float*)sym(g_agg_f0);
    float* agg_f1 = (float*)sym(g_agg_f1);
    float* agg_h0 = (float*)sym(g_agg_h0);
    float* agg_h1 = (float*)sym(g_agg_h1);
    float* f_buf1 = (float*)sym(g_f_buf1);
    float* f_buf2 = (float*)sym(g_f_buf2);
    float* h_buf1 = (float*)sym(g_h_buf1);
    float* h_buf2 = (float*)sym(g_h_buf2);
    float* inv_sends = (float*)sym(g_inv_sends);
    float* inv_prec  = (float*)sym(g_inv_prec);
    float* inv_rev   = (float*)sym(g_inv_rev);
    float* inv_reach = (float*)sym(g_inv_reach);
    float* Beff  = (float*)sym(g_Beff);
    float* biasp = (float*)sym(g_bias);
    float* stats = (float*)sym(g_stats);

    // ---- degrees (independent of block) ----
    cudaMemsetAsync(inv_sends, 0, (size_t)NF * 4);
    cudaMemsetAsync(inv_prec, 0, (size_t)NF * 4);
    cudaMemsetAsync(inv_rev, 0, (size_t)NH * 4);
    cudaMemsetAsync(inv_reach, 0, (size_t)NH * 4);
    count_deg<<<(E_sends + 255) / 256, 256>>>(ei_sends, E_sends, inv_sends);
    count_deg<<<(E_prec + 255) / 256, 256>>>(ei_prec, E_prec, inv_prec);
    count_deg<<<(E_rev + 255) / 256, 256>>>(ei_rev, E_rev, inv_rev);
    count_deg<<<(E_reach + 255) / 256, 256>>>(ei_reach, E_reach, inv_reach);
    invert_cnt<<<(NF + 255) / 256, 256>>>(inv_sends, NF);
    invert_cnt<<<(NF + 255) / 256, 256>>>(inv_prec, NF);
    invert_cnt<<<(NH + 255) / 256, 256>>>(inv_rev, NH);
    invert_cnt<<<(NH + 255) / 256, 256>>>(inv_reach, NH);

    // ---- fused weights ----
    {
        int tot = 2 * 2 * 384 * HDIM;
        prep_weights<<<(tot + 255) / 256, 256>>>(W_l, b_l, W_r, Beff, biasp);
    }

    const int gemm_grid_f = (NF + 127) / 128;
    const int gemm_grid_h = (NH + 127) / 128;

    const float* h_cur = x_host;
    const float* f_cur = x_flow;

    for (int blk = 0; blk < NUM_BLOCKS; blk++) {
        float* f_next = blk == 0 ? f_buf1 : f_buf2;
        float* h_next = blk == 0 ? h_buf1 : h_buf2;

        cudaMemsetAsync(agg_f0, 0, (size_t)NF * HDIM * 4);
        cudaMemsetAsync(agg_f1, 0, (size_t)NF * HDIM * 4);
        cudaMemsetAsync(agg_h0, 0, (size_t)NH * HDIM * 4);
        cudaMemsetAsync(agg_h1, 0, (size_t)NH * HDIM * 4);

        // scatter: 8 edges per 256-thread block (32 lanes/edge)
        scatter_add<<<(E_sends + 7) / 8, 256>>>(h_cur, ei_sends, E_sends, agg_f0);
        scatter_add<<<(E_prec + 7) / 8, 256>>>(f_cur, ei_prec, E_prec, agg_f1);
        scatter_add<<<(E_rev + 7) / 8, 256>>>(f_cur, ei_rev, E_rev, agg_h0);
        scatter_add<<<(E_reach + 7) / 8, 256>>>(f_cur, ei_reach, E_reach, agg_h1);

        // fused GEMMs
        const float* Bf = Beff + (size_t)(blk * 2 + 0) * 384 * HDIM;
        const float* Bh = Beff + (size_t)(blk * 2 + 1) * 384 * HDIM;
        const float* bf = biasp + (blk * 2 + 0) * HDIM;
        const float* bh = biasp + (blk * 2 + 1) * HDIM;
        fused_gemm<<<gemm_grid_f, 256>>>(agg_f0, inv_sends, agg_f1, inv_prec, f_cur,
                                         Bf, bf, f_next, NF);
        fused_gemm<<<gemm_grid_h, 256>>>(agg_h0, inv_rev, agg_h1, inv_reach, h_cur,
                                         Bh, bh, h_next, NH);

        // BN + LeakyReLU
        cudaMemsetAsync(stats, 0, 4 * HDIM * 4);
        bn_stats<<<1024, 256>>>(h_next, NH, stats, stats + HDIM);
        bn_stats<<<1024, 256>>>(f_next, NF, stats + 2 * HDIM, stats + 3 * HDIM);

        const float* gamma = bn_gamma + blk * HDIM;
        const float* beta  = bn_beta + blk * HDIM;
        float* h_out = (blk == NUM_BLOCKS - 1) ? out : h_next;
        float* f_out = (blk == NUM_BLOCKS - 1) ? (out + (size_t)NH * HDIM) : f_next;
        {
            size_t tot = (size_t)NH * HDIM;
            bn_apply<<<(int)((tot + 255) / 256), 256>>>(h_next, h_out, NH, stats,
                                                        stats + HDIM, gamma, beta);
        }
        {
            size_t tot = (size_t)NF * HDIM;
            bn_apply<<<(int)((tot + 255) / 256), 256>>>(f_next, f_out, NF, stats + 2 * HDIM,
                                                        stats + 3 * HDIM, gamma, beta);
        }

        h_cur = h_next;
        f_cur = f_next;
    }
}

// round 9
// speedup vs baseline: 1.0470x; 1.0470x over previous
#include <cuda_runtime.h>
#include <mma.h>
#include <cstdint>
#include <cstddef>

using namespace nvcuda;

#define NH 50000
#define NF 200000
#define HDIM 128
#define NUM_BLOCKS 2

// ---------------- scratch (device globals; no allocations allowed) ----------------
__device__ float g_agg_f0[(size_t)NF * HDIM];   // sends mean (dst=flow), inv folded in
__device__ float g_agg_f1[(size_t)NF * HDIM];   // precedes mean (dst=flow)
__device__ float g_agg_h0[(size_t)NH * HDIM];   // rev_sends mean (dst=host)
__device__ float g_agg_h1[(size_t)NH * HDIM];   // reaches mean (dst=host)
__device__ float g_f_buf1[(size_t)NF * HDIM];
__device__ float g_f_buf2[(size_t)NF * HDIM];
__device__ float g_h_buf1[(size_t)NH * HDIM];
__device__ float g_h_buf2[(size_t)NH * HDIM];
__device__ float g_inv_sends[NF];
__device__ float g_inv_prec[NF];
__device__ float g_inv_rev[NH];
__device__ float g_inv_reach[NH];
__device__ float g_Bt[2 * 2 * 128 * 384];       // [blk][type(f=0,h=1)][n=128][k=384] K-major
__device__ float g_stats[4 * HDIM];             // hsum, hsq, fsum, fsq

// ---------------- kernels ----------------

__global__ void count_deg(const int* __restrict__ ei, int E, float* __restrict__ cnt) {
    int e = blockIdx.x * blockDim.x + threadIdx.x;
    if (e < E) atomicAdd(&cnt[ei[E + e]], 1.0f);
}

__global__ void invert_cnt(float* __restrict__ c, int n) {
    int i = blockIdx.x * blockDim.x + threadIdx.x;
    if (i < n) c[i] = 1.0f / fmaxf(c[i], 1.0f);
}

// Each warp handles one edge; lane l moves 4 consecutive floats via vector red.
// inv[dst] is folded in: agg accumulates the MEAN directly.
__global__ void scatter_add(const float* __restrict__ src, const int* __restrict__ ei,
                            int E, const float* __restrict__ inv, float* __restrict__ agg) {
    int lane = threadIdx.x & 31;
    int e = (blockIdx.x * blockDim.x + threadIdx.x) >> 5;
    if (e >= E) return;
    int s = ei[e];
    int d = ei[E + e];
    float iv = __ldg(&inv[d]);   // broadcast across warp
    float4 v = *(const float4*)(src + (size_t)s * HDIM + lane * 4);
    v.x *= iv; v.y *= iv; v.z *= iv; v.w *= iv;
    float* drow = agg + (size_t)d * HDIM + lane * 4;
    asm volatile("red.global.add.v4.f32 [%0], {%1,%2,%3,%4};"
                 :: "l"(drow), "f"(v.x), "f"(v.y), "f"(v.z), "f"(v.w) : "memory");
}

// Build fused B matrices: Bt[blk][type][n][k], k = [Wl_a row | Wl_b row | (Wr_a+Wr_b) row],
// all scaled by 0.5. (Biases dropped: a per-channel constant pre-BN cancels exactly.)
__global__ void prep_weights(const float* __restrict__ Wl, const float* __restrict__ Wr,
                             float* __restrict__ Bt) {
    int i = blockIdx.x * blockDim.x + threadIdx.x;
    const int total = 2 * 2 * 128 * 384;
    if (i >= total) return;
    int k = i % 384;
    int n = (i / 384) & 127;
    int t = (i / (384 * 128)) & 1;
    int b = i / (384 * 128 * 2);
    int ta = t ? 1 : 0, tb = t ? 3 : 2;
    int seg = k >> 7, kk = k & 127;
    float v;
    if (seg == 0)      v = Wl[(((size_t)b * 4 + ta) * 128 + n) * 128 + kk];
    else if (seg == 1) v = Wl[(((size_t)b * 4 + tb) * 128 + n) * 128 + kk];
    else               v = Wr[(((size_t)b * 4 + ta) * 128 + n) * 128 + kk]
                         + Wr[(((size_t)b * 4 + tb) * 128 + n) * 128 + kk];
    Bt[i] = 0.5f * v;
}

// WMMA tf32 GEMM: out[r][o] = sum_k Aeff[r][k] * Bt[o][k]
// Aeff segments along K: agg0 (k 0..127) | agg1 (128..255) | x (256..383); means prefolded.
// Block: 256 thr = 8 warps; warp owns 16 rows x 128 cols. B chunk (128n x 32k) staged in smem.
// NH, NF are multiples of 16 -> each warp strip is fully valid or fully OOB.
__global__ __launch_bounds__(256) void gemm_wmma(
    const float* __restrict__ A0, const float* __restrict__ A1, const float* __restrict__ A2,
    const float* __restrict__ Bt, float* __restrict__ out, int nrows)
{
    __shared__ float Bs[128 * 36];    // [n][k] col-major tiles, ldm=36 (pad: 2-way max)
    const int tid = threadIdx.x;
    const int wid = tid >> 5;
    const int wrow = blockIdx.x * 128 + wid * 16;
    const bool wvalid = wrow < nrows;

    wmma::fragment<wmma::accumulator, 16, 16, 8, float> acc[8];
#pragma unroll
    for (int nt = 0; nt < 8; nt++) wmma::fill_fragment(acc[nt], 0.0f);

    for (int chunk = 0; chunk < 12; chunk++) {
        const float* Asrc = (chunk < 4) ? A0 : (chunk < 8) ? A1 : A2;
        const int kbase = chunk * 32;          // k offset within Bt row
        const int koff = (chunk & 3) * 32;     // k offset within segment array

        // stage B chunk: 128 n-rows x 32 k floats
#pragma unroll
        for (int i = 0; i < 4; i++) {
            int idx = tid + i * 256;           // float4 units, 0..1023
            int n = idx >> 3, q = idx & 7;
            *(float4*)&Bs[n * 36 + q * 4] =
                *(const float4*)(Bt + (size_t)n * 384 + kbase + q * 4);
        }
        __syncthreads();

        if (wvalid) {
#pragma unroll
            for (int kk = 0; kk < 4; kk++) {
                wmma::fragment<wmma::matrix_a, 16, 16, 8, wmma::precision::tf32,
                               wmma::row_major> a;
                wmma::load_matrix_sync(a, Asrc + (size_t)wrow * HDIM + koff + kk * 8, HDIM);
#pragma unroll
                for (int t = 0; t < a.num_elements; t++)
                    a.x[t] = wmma::__float_to_tf32(a.x[t]);
#pragma unroll
                for (int nt = 0; nt < 8; nt++) {
                    wmma::fragment<wmma::matrix_b, 16, 16, 8, wmma::precision::tf32,
                                   wmma::col_major> b;
                    wmma::load_matrix_sync(b, Bs + nt * 16 * 36 + kk * 8, 36);
#pragma unroll
                    for (int t = 0; t < b.num_elements; t++)
                        b.x[t] = wmma::__float_to_tf32(b.x[t]);
                    wmma::mma_sync(acc[nt], a, b, acc[nt]);
                }
            }
        }
        __syncthreads();
    }

    if (wvalid) {
#pragma unroll
        for (int nt = 0; nt < 8; nt++)
            wmma::store_matrix_sync(out + (size_t)wrow * HDIM + nt * 16, acc[nt],
                                    HDIM, wmma::mem_row_major);
    }
}

__global__ void bn_stats(const float* __restrict__ v, int n,
                         float* __restrict__ sum, float* __restrict__ sq) {
    int c = threadIdx.x & 127;
    int sub = threadIdx.x >> 7;  // 0..1
    float s = 0.f, s2 = 0.f;
    for (int r = blockIdx.x * 2 + sub; r < n; r += gridDim.x * 2) {
        float x = v[(size_t)r * HDIM + c];
        s += x;
        s2 += x * x;
    }
    __shared__ float sh[256], sh2[256];
    sh[threadIdx.x] = s;
    sh2[threadIdx.x] = s2;
    __syncthreads();
    if (sub == 0) {
        atomicAdd(&sum[c], sh[c] + sh[c + 128]);
        atomicAdd(&sq[c], sh2[c] + sh2[c + 128]);
    }
}

__global__ void bn_apply(const float* __restrict__ in, float* __restrict__ out, int n,
                         const float* __restrict__ sum, const float* __restrict__ sq,
                         const float* __restrict__ gamma, const float* __restrict__ beta) {
    size_t i = (size_t)blockIdx.x * blockDim.x + threadIdx.x;
    size_t total = (size_t)n * HDIM;
    if (i >= total) return;
    int c = (int)(i & 127);
    float N = (float)n;
    float mu = sum[c] / N;
    float var = sq[c] / N - mu * mu;
    float rstd = rsqrtf(var + 1e-5f);
    float x = (in[i] - mu) * rstd * gamma[c] + beta[c];
    out[i] = x >= 0.f ? x : 0.01f * x;
}

// ---------------- host ----------------
static inline void* sym(const void* s) {
    void* p = 0;
    cudaGetSymbolAddress(&p, s);
    return p;
}

extern "C" void kernel_launch(void* const* d_in, const int* in_sizes, int n_in,
                              void* d_out, int out_size) {
    const float* x_host = (const float*)d_in[0];
    const float* x_flow = (const float*)d_in[1];
    const int* ei_sends = (const int*)d_in[2];
    const int* ei_rev   = (const int*)d_in[3];
    const int* ei_prec  = (const int*)d_in[4];
    const int* ei_reach = (const int*)d_in[5];
    const float* W_l = (const float*)d_in[6];
    const float* W_r = (const float*)d_in[8];
    const float* bn_gamma = (const float*)d_in[9];
    const float* bn_beta  = (const float*)d_in[10];
    float* out = (float*)d_out;

    int E_sends = in_sizes[2] / 2;
    int E_rev   = in_sizes[3] / 2;
    int E_prec  = in_sizes[4] / 2;
    int E_reach = in_sizes[5] / 2;

    float* agg_f0 = (float*)sym(g_agg_f0);
    float* agg_f1 = (float*)sym(g_agg_f1);
    float* agg_h0 = (float*)sym(g_agg_h0);
    float* agg_h1 = (float*)sym(g_agg_h1);
    float* f_buf1 = (float*)sym(g_f_buf1);
    float* f_buf2 = (float*)sym(g_f_buf2);
    float* h_buf1 = (float*)sym(g_h_buf1);
    float* h_buf2 = (float*)sym(g_h_buf2);
    float* inv_sends = (float*)sym(g_inv_sends);
    float* inv_prec  = (float*)sym(g_inv_prec);
    float* inv_rev   = (float*)sym(g_inv_rev);
    float* inv_reach = (float*)sym(g_inv_reach);
    float* Bt    = (float*)sym(g_Bt);
    float* stats = (float*)sym(g_stats);

    // ---- degrees (independent of block) ----
    cudaMemsetAsync(inv_sends, 0, (size_t)NF * 4);
    cudaMemsetAsync(inv_prec, 0, (size_t)NF * 4);
    cudaMemsetAsync(inv_rev, 0, (size_t)NH * 4);
    cudaMemsetAsync(inv_reach, 0, (size_t)NH * 4);
    count_deg<<<(E_sends + 255) / 256, 256>>>(ei_sends, E_sends, inv_sends);
    count_deg<<<(E_prec + 255) / 256, 256>>>(ei_prec, E_prec, inv_prec);
    count_deg<<<(E_rev + 255) / 256, 256>>>(ei_rev, E_rev, inv_rev);
    count_deg<<<(E_reach + 255) / 256, 256>>>(ei_reach, E_reach, inv_reach);
    invert_cnt<<<(NF + 255) / 256, 256>>>(inv_sends, NF);
    invert_cnt<<<(NF + 255) / 256, 256>>>(inv_prec, NF);
    invert_cnt<<<(NH + 255) / 256, 256>>>(inv_rev, NH);
    invert_cnt<<<(NH + 255) / 256, 256>>>(inv_reach, NH);

    // ---- fused weights (K-major Bt) ----
    {
        int tot = 2 * 2 * 128 * 384;
        prep_weights<<<(tot + 255) / 256, 256>>>(W_l, W_r, Bt);
    }

    const int gemm_grid_f = (NF + 127) / 128;
    const int gemm_grid_h = (NH + 127) / 128;

    const float* h_cur = x_host;
    const float* f_cur = x_flow;

    for (int blk = 0; blk < NUM_BLOCKS; blk++) {
        float* f_next = blk == 0 ? f_buf1 : f_buf2;
        float* h_next = blk == 0 ? h_buf1 : h_buf2;

        cudaMemsetAsync(agg_f0, 0, (size_t)NF * HDIM * 4);
        cudaMemsetAsync(agg_f1, 0, (size_t)NF * HDIM * 4);
        cudaMemsetAsync(agg_h0, 0, (size_t)NH * HDIM * 4);
        cudaMemsetAsync(agg_h1, 0, (size_t)NH * HDIM * 4);

        // scatter: 8 edges per 256-thread block (32 lanes/edge), mean folded in
        scatter_add<<<(E_sends + 7) / 8, 256>>>(h_cur, ei_sends, E_sends, inv_sends, agg_f0);
        scatter_add<<<(E_prec + 7) / 8, 256>>>(f_cur, ei_prec, E_prec, inv_prec, agg_f1);
        scatter_add<<<(E_rev + 7) / 8, 256>>>(f_cur, ei_rev, E_rev, inv_rev, agg_h0);
        scatter_add<<<(E_reach + 7) / 8, 256>>>(f_cur, ei_reach, E_reach, inv_reach, agg_h1);

        // fused tf32 WMMA GEMMs
        const float* Bf = Bt + (size_t)(blk * 2 + 0) * 128 * 384;
        const float* Bh = Bt + (size_t)(blk * 2 + 1) * 128 * 384;
        gemm_wmma<<<gemm_grid_f, 256>>>(agg_f0, agg_f1, f_cur, Bf, f_next, NF);
        gemm_wmma<<<gemm_grid_h, 256>>>(agg_h0, agg_h1, h_cur, Bh, h_next, NH);

        // BN + LeakyReLU
        cudaMemsetAsync(stats, 0, 4 * HDIM * 4);
        bn_stats<<<1024, 256>>>(h_next, NH, stats, stats + HDIM);
        bn_stats<<<1024, 256>>>(f_next, NF, stats + 2 * HDIM, stats + 3 * HDIM);

        const float* gamma = bn_gamma + blk * HDIM;
        const float* beta  = bn_beta + blk * HDIM;
        float* h_out = (blk == NUM_BLOCKS - 1) ? out : h_next;
        float* f_out = (blk == NUM_BLOCKS - 1) ? (out + (size_t)NH * HDIM) : f_next;
        {
            size_t tot = (size_t)NH * HDIM;
            bn_apply<<<(int)((tot + 255) / 256), 256>>>(h_next, h_out, NH, stats,
                                                        stats + HDIM, gamma, beta);
        }
        {
            size_t tot = (size_t)NF * HDIM;
            bn_apply<<<(int)((tot + 255) / 256), 256>>>(f_next, f_out, NF, stats + 2 * HDIM,
                                                        stats + 3 * HDIM, gamma, beta);
        }

        h_cur = h_next;
        f_cur = f_next;
    }
}

// round 10
// speedup vs baseline: 1.1066x; 1.0570x over previous
#include <cuda_runtime.h>
#include <mma.h>
#include <cstdint>
#include <cstddef>

using namespace nvcuda;

#define NH 50000
#define NF 200000
#define HDIM 128
#define NUM_BLOCKS 2

#define E_SENDS_MAX 1000000
#define E_PREC_MAX  2000000

// ---------------- scratch (device globals; no allocations allowed) ----------------
__device__ float g_agg_f0[(size_t)NF * HDIM];   // sends mean (dst=flow)
__device__ float g_agg_f1[(size_t)NF * HDIM];   // precedes mean (dst=flow)
__device__ float g_agg_h0[(size_t)NH * HDIM];   // rev_sends mean (dst=host)
__device__ float g_agg_h1[(size_t)NH * HDIM];   // reaches mean (dst=host)
__device__ float g_f_buf1[(size_t)NF * HDIM];
__device__ float g_f_buf2[(size_t)NF * HDIM];
__device__ float g_h_buf1[(size_t)NH * HDIM];
__device__ float g_h_buf2[(size_t)NH * HDIM];
__device__ float g_Bt[2 * 2 * 128 * 384];       // [blk][type(f=0,h=1)][n=128][k=384] K-major
__device__ float g_stats[4 * HDIM];             // hsum, hsq, fsum, fsq

// CSR scratch (built once per launch; edge lists are loop-invariant)
__device__ int g_deg[NF];                        // reused per type
__device__ int g_ptr_sends[NF + 1];
__device__ int g_ptr_prec[NF + 1];
__device__ int g_ptr_rev[NH + 1];
__device__ int g_ptr_reach[NH + 1];
__device__ int g_next[NF + 1];                   // fill cursors (reused per type)
__device__ int g_col_sends[E_SENDS_MAX];
__device__ int g_col_prec[E_PREC_MAX];
__device__ int g_col_rev[E_SENDS_MAX];
__device__ int g_col_reach[E_SENDS_MAX];

// ---------------- CSR build kernels ----------------

__global__ void hist_deg(const int* __restrict__ ei, int E, int* __restrict__ deg) {
    int e = blockIdx.x * blockDim.x + threadIdx.x;
    if (e < E) atomicAdd(&deg[ei[E + e]], 1);
}

// Single-block exclusive scan of deg[0..n) -> ptr[0..n]; also writes next[i]=ptr[i].
__global__ void scan_excl(const int* __restrict__ deg, int* __restrict__ ptr,
                          int* __restrict__ next, int n) {
    __shared__ int part[1024];
    const int tid = threadIdx.x;
    const int seg = (n + 1023) / 1024;
    const int lo = tid * seg;
    const int hi = min(n, lo + seg);
    int s = 0;
    for (int i = lo; i < hi; i++) s += deg[i];
    part[tid] = s;
    __syncthreads();
    if (tid == 0) {
        int run = 0;
        for (int i = 0; i < 1024; i++) { int v = part[i]; part[i] = run; run += v; }
    }
    __syncthreads();
    int run = part[tid];
    for (int i = lo; i < hi; i++) {
        ptr[i] = run;
        next[i] = run;
        run += deg[i];
    }
    if (hi == n && lo <= n) ptr[n] = run;   // last active thread writes total
}

__global__ void fill_csr(const int* __restrict__ ei, int E,
                         int* __restrict__ next, int* __restrict__ col) {
    int e = blockIdx.x * blockDim.x + threadIdx.x;
    if (e >= E) return;
    int s = ei[e];
    int d = ei[E + e];
    int pos = atomicAdd(&next[d], 1);
    col[pos] = s;
}

// ---------------- aggregation: warp-per-dst gather, mean folded in ----------------
__global__ __launch_bounds__(256) void gather_mean(
    const float* __restrict__ src, const int* __restrict__ ptr,
    const int* __restrict__ col, int n, float* __restrict__ agg)
{
    const int w = (blockIdx.x * blockDim.x + threadIdx.x) >> 5;
    if (w >= n) return;
    const int lane = threadIdx.x & 31;
    const int s0 = __ldg(&ptr[w]);
    const int s1 = __ldg(&ptr[w + 1]);
    float4 a0 = make_float4(0.f, 0.f, 0.f, 0.f);
    float4 a1 = make_float4(0.f, 0.f, 0.f, 0.f);
    int e = s0;
    for (; e + 1 < s1; e += 2) {
        int sA = __ldg(&col[e]);
        int sB = __ldg(&col[e + 1]);
        float4 vA = *(const float4*)(src + (size_t)sA * HDIM + lane * 4);
        float4 vB = *(const float4*)(src + (size_t)sB * HDIM + lane * 4);
        a0.x += vA.x; a0.y += vA.y; a0.z += vA.z; a0.w += vA.w;
        a1.x += vB.x; a1.y += vB.y; a1.z += vB.z; a1.w += vB.w;
    }
    if (e < s1) {
        int sA = __ldg(&col[e]);
        float4 vA = *(const float4*)(src + (size_t)sA * HDIM + lane * 4);
        a0.x += vA.x; a0.y += vA.y; a0.z += vA.z; a0.w += vA.w;
    }
    float inv = 1.0f / (float)max(s1 - s0, 1);
    float4 r;
    r.x = (a0.x + a1.x) * inv;
    r.y = (a0.y + a1.y) * inv;
    r.z = (a0.z + a1.z) * inv;
    r.w = (a0.w + a1.w) * inv;
    *(float4*)(agg + (size_t)w * HDIM + lane * 4) = r;
}

// ---------------- weights ----------------
// Bt[blk][type][n][k], k = [Wl_a row | Wl_b row | (Wr_a+Wr_b) row], scaled by 0.5.
// (Biases dropped: per-channel constants pre-BN cancel exactly in mean subtraction.)
__global__ void prep_weights(const float* __restrict__ Wl, const float* __restrict__ Wr,
                             float* __restrict__ Bt) {
    int i = blockIdx.x * blockDim.x + threadIdx.x;
    const int total = 2 * 2 * 128 * 384;
    if (i >= total) return;
    int k = i % 384;
    int n = (i / 384) & 127;
    int t = (i / (384 * 128)) & 1;
    int b = i / (384 * 128 * 2);
    int ta = t ? 1 : 0, tb = t ? 3 : 2;
    int seg = k >> 7, kk = k & 127;
    float v;
    if (seg == 0)      v = Wl[(((size_t)b * 4 + ta) * 128 + n) * 128 + kk];
    else if (seg == 1) v = Wl[(((size_t)b * 4 + tb) * 128 + n) * 128 + kk];
    else               v = Wr[(((size_t)b * 4 + ta) * 128 + n) * 128 + kk]
                         + Wr[(((size_t)b * 4 + tb) * 128 + n) * 128 + kk];
    Bt[i] = 0.5f * v;
}

// ---------------- WMMA tf32 GEMM: out[r][o] = sum_k Aeff[r][k] * Bt[o][k] ----------------
// Aeff segments along K: agg0 (0..127) | agg1 (128..255) | x (256..383); means prefolded.
__global__ __launch_bounds__(256) void gemm_wmma(
    const float* __restrict__ A0, const float* __restrict__ A1, const float* __restrict__ A2,
    const float* __restrict__ Bt, float* __restrict__ out, int nrows)
{
    __shared__ float Bs[128 * 36];
    const int tid = threadIdx.x;
    const int wid = tid >> 5;
    const int wrow = blockIdx.x * 128 + wid * 16;
    const bool wvalid = wrow < nrows;

    wmma::fragment<wmma::accumulator, 16, 16, 8, float> acc[8];
#pragma unroll
    for (int nt = 0; nt < 8; nt++) wmma::fill_fragment(acc[nt], 0.0f);

    for (int chunk = 0; chunk < 12; chunk++) {
        const float* Asrc = (chunk < 4) ? A0 : (chunk < 8) ? A1 : A2;
        const int kbase = chunk * 32;
        const int koff = (chunk & 3) * 32;

#pragma unroll
        for (int i = 0; i < 4; i++) {
            int idx = tid + i * 256;
            int n = idx >> 3, q = idx & 7;
            *(float4*)&Bs[n * 36 + q * 4] =
                *(const float4*)(Bt + (size_t)n * 384 + kbase + q * 4);
        }
        __syncthreads();

        if (wvalid) {
#pragma unroll
            for (int kk = 0; kk < 4; kk++) {
                wmma::fragment<wmma::matrix_a, 16, 16, 8, wmma::precision::tf32,
                               wmma::row_major> a;
                wmma::load_matrix_sync(a, Asrc + (size_t)wrow * HDIM + koff + kk * 8, HDIM);
#pragma unroll
                for (int t = 0; t < a.num_elements; t++)
                    a.x[t] = wmma::__float_to_tf32(a.x[t]);
#pragma unroll
                for (int nt = 0; nt < 8; nt++) {
                    wmma::fragment<wmma::matrix_b, 16, 16, 8, wmma::precision::tf32,
                                   wmma::col_major> b;
                    wmma::load_matrix_sync(b, Bs + nt * 16 * 36 + kk * 8, 36);
#pragma unroll
                    for (int t = 0; t < b.num_elements; t++)
                        b.x[t] = wmma::__float_to_tf32(b.x[t]);
                    wmma::mma_sync(acc[nt], a, b, acc[nt]);
                }
            }
        }
        __syncthreads();
    }

    if (wvalid) {
#pragma unroll
        for (int nt = 0; nt < 8; nt++)
            wmma::store_matrix_sync(out + (size_t)wrow * HDIM + nt * 16, acc[nt],
                                    HDIM, wmma::mem_row_major);
    }
}

// ---------------- BN + LeakyReLU ----------------
__global__ void bn_stats(const float* __restrict__ v, int n,
                         float* __restrict__ sum, float* __restrict__ sq) {
    int c = threadIdx.x & 127;
    int sub = threadIdx.x >> 7;
    float s = 0.f, s2 = 0.f;
    for (int r = blockIdx.x * 2 + sub; r < n; r += gridDim.x * 2) {
        float x = v[(size_t)r * HDIM + c];
        s += x;
        s2 += x * x;
    }
    __shared__ float sh[256], sh2[256];
    sh[threadIdx.x] = s;
    sh2[threadIdx.x] = s2;
    __syncthreads();
    if (sub == 0) {
        atomicAdd(&sum[c], sh[c] + sh[c + 128]);
        atomicAdd(&sq[c], sh2[c] + sh2[c + 128]);
    }
}

__global__ void bn_apply(const float* __restrict__ in, float* __restrict__ out, int n,
                         const float* __restrict__ sum, const float* __restrict__ sq,
                         const float* __restrict__ gamma, const float* __restrict__ beta) {
    size_t i = (size_t)blockIdx.x * blockDim.x + threadIdx.x;
    size_t total = (size_t)n * HDIM;
    if (i >= total) return;
    int c = (int)(i & 127);
    float N = (float)n;
    float mu = sum[c] / N;
    float var = sq[c] / N - mu * mu;
    float rstd = rsqrtf(var + 1e-5f);
    float x = (in[i] - mu) * rstd * gamma[c] + beta[c];
    out[i] = x >= 0.f ? x : 0.01f * x;
}

// ---------------- host ----------------
static inline void* sym(const void* s) {
    void* p = 0;
    cudaGetSymbolAddress(&p, s);
    return p;
}

extern "C" void kernel_launch(void* const* d_in, const int* in_sizes, int n_in,
                              void* d_out, int out_size) {
    const float* x_host = (const float*)d_in[0];
    const float* x_flow = (const float*)d_in[1];
    const int* ei_sends = (const int*)d_in[2];
    const int* ei_rev   = (const int*)d_in[3];
    const int* ei_prec  = (const int*)d_in[4];
    const int* ei_reach = (const int*)d_in[5];
    const float* W_l = (const float*)d_in[6];
    const float* W_r = (const float*)d_in[8];
    const float* bn_gamma = (const float*)d_in[9];
    const float* bn_beta  = (const float*)d_in[10];
    float* out = (float*)d_out;

    int E_sends = in_sizes[2] / 2;
    int E_rev   = in_sizes[3] / 2;
    int E_prec  = in_sizes[4] / 2;
    int E_reach = in_sizes[5] / 2;

    float* agg_f0 = (float*)sym(g_agg_f0);
    float* agg_f1 = (float*)sym(g_agg_f1);
    float* agg_h0 = (float*)sym(g_agg_h0);
    float* agg_h1 = (float*)sym(g_agg_h1);
    float* f_buf1 = (float*)sym(g_f_buf1);
    float* f_buf2 = (float*)sym(g_f_buf2);
    float* h_buf1 = (float*)sym(g_h_buf1);
    float* h_buf2 = (float*)sym(g_h_buf2);
    float* Bt    = (float*)sym(g_Bt);
    float* stats = (float*)sym(g_stats);

    int* deg       = (int*)sym(g_deg);
    int* ptr_sends = (int*)sym(g_ptr_sends);
    int* ptr_prec  = (int*)sym(g_ptr_prec);
    int* ptr_rev   = (int*)sym(g_ptr_rev);
    int* ptr_reach = (int*)sym(g_ptr_reach);
    int* nxt       = (int*)sym(g_next);
    int* col_sends = (int*)sym(g_col_sends);
    int* col_prec  = (int*)sym(g_col_prec);
    int* col_rev   = (int*)sym(g_col_rev);
    int* col_reach = (int*)sym(g_col_reach);

    // ---- CSR build (once; edge lists are loop-invariant) ----
    struct { const int* ei; int E; int n; int* ptr; int* col; } T[4] = {
        { ei_sends, E_sends, NF, ptr_sends, col_sends },
        { ei_prec,  E_prec,  NF, ptr_prec,  col_prec  },
        { ei_rev,   E_rev,   NH, ptr_rev,   col_rev   },
        { ei_reach, E_reach, NH, ptr_reach, col_reach },
    };
    for (int t = 0; t < 4; t++) {
        cudaMemsetAsync(deg, 0, (size_t)T[t].n * sizeof(int));
        hist_deg<<<(T[t].E + 255) / 256, 256>>>(T[t].ei, T[t].E, deg);
        scan_excl<<<1, 1024>>>(deg, T[t].ptr, nxt, T[t].n);
        fill_csr<<<(T[t].E + 255) / 256, 256>>>(T[t].ei, T[t].E, nxt, T[t].col);
    }

    // ---- fused weights (K-major Bt) ----
    {
        int tot = 2 * 2 * 128 * 384;
        prep_weights<<<(tot + 255) / 256, 256>>>(W_l, W_r, Bt);
    }

    const int gemm_grid_f = (NF + 127) / 128;
    const int gemm_grid_h = (NH + 127) / 128;
    const int gat_grid_f = (NF * 32 + 255) / 256;
    const int gat_grid_h = (NH * 32 + 255) / 256;

    const float* h_cur = x_host;
    const float* f_cur = x_flow;

    for (int blk = 0; blk < NUM_BLOCKS; blk++) {
        float* f_next = blk == 0 ? f_buf1 : f_buf2;
        float* h_next = blk == 0 ? h_buf1 : h_buf2;

        // gather-aggregate (atomic-free, no memsets, mean folded in)
        gather_mean<<<gat_grid_f, 256>>>(h_cur, ptr_sends, col_sends, NF, agg_f0);
        gather_mean<<<gat_grid_f, 256>>>(f_cur, ptr_prec, col_prec, NF, agg_f1);
        gather_mean<<<gat_grid_h, 256>>>(f_cur, ptr_rev, col_rev, NH, agg_h0);
        gather_mean<<<gat_grid_h, 256>>>(f_cur, ptr_reach, col_reach, NH, agg_h1);

        // fused tf32 WMMA GEMMs
        const float* Bf = Bt + (size_t)(blk * 2 + 0) * 128 * 384;
        const float* Bh = Bt + (size_t)(blk * 2 + 1) * 128 * 384;
        gemm_wmma<<<gemm_grid_f, 256>>>(agg_f0, agg_f1, f_cur, Bf, f_next, NF);
        gemm_wmma<<<gemm_grid_h, 256>>>(agg_h0, agg_h1, h_cur, Bh, h_next, NH);

        // BN + LeakyReLU
        cudaMemsetAsync(stats, 0, 4 * HDIM * 4);
        bn_stats<<<1024, 256>>>(h_next, NH, stats, stats + HDIM);
        bn_stats<<<1024, 256>>>(f_next, NF, stats + 2 * HDIM, stats + 3 * HDIM);

        const float* gamma = bn_gamma + blk * HDIM;
        const float* beta  = bn_beta + blk * HDIM;
        float* h_out = (blk == NUM_BLOCKS - 1) ? out : h_next;
        float* f_out = (blk == NUM_BLOCKS - 1) ? (out + (size_t)NH * HDIM) : f_next;
        {
            size_t tot = (size_t)NH * HDIM;
            bn_apply<<<(int)((tot + 255) / 256), 256>>>(h_next, h_out, NH, stats,
                                                        stats + HDIM, gamma, beta);
        }
        {
            size_t tot = (size_t)NF * HDIM;
            bn_apply<<<(int)((tot + 255) / 256), 256>>>(f_next, f_out, NF, stats + 2 * HDIM,
                                                        stats + 3 * HDIM, gamma, beta);
        }

        h_cur = h_next;
        f_cur = f_next;
    }
}

// round 11
// speedup vs baseline: 1.1337x; 1.0244x over previous
#include <cuda_runtime.h>
#include <mma.h>
#include <cstdint>
#include <cstddef>

using namespace nvcuda;

#define NH 50000
#define NF 200000
#define HDIM 128
#define NUM_BLOCKS 2

#define E_SENDS_MAX 1000000
#define E_PREC_MAX  2000000

// ---------------- scratch (device globals; no allocations allowed) ----------------
__device__ float g_agg_f0[(size_t)NF * HDIM];
__device__ float g_agg_f1[(size_t)NF * HDIM];
__device__ float g_agg_h0[(size_t)NH * HDIM];
__device__ float g_agg_h1[(size_t)NH * HDIM];
__device__ float g_f_buf1[(size_t)NF * HDIM];
__device__ float g_f_buf2[(size_t)NF * HDIM];
__device__ float g_h_buf1[(size_t)NH * HDIM];
__device__ float g_h_buf2[(size_t)NH * HDIM];
__device__ float g_Bt[2 * 2 * 128 * 384];       // [blk][type][n=128][k=384] K-major
__device__ float g_stats[4 * HDIM];

// CSR scratch (built once per launch)
__device__ int g_deg[NF];
__device__ int g_ptr_sends[NF + 1];
__device__ int g_ptr_prec[NF + 1];
__device__ int g_ptr_rev[NH + 1];
__device__ int g_ptr_reach[NH + 1];
__device__ int g_next[NF + 1];
__device__ int g_col_sends[E_SENDS_MAX];
__device__ int g_col_prec[E_PREC_MAX];
__device__ int g_col_rev[E_SENDS_MAX];
__device__ int g_col_reach[E_SENDS_MAX];

// ---------------- cache-hinted accessors ----------------
__device__ __forceinline__ void stcs4(float* p, float4 v) {
    asm volatile("st.global.cs.v4.f32 [%0], {%1,%2,%3,%4};"
                 :: "l"(p), "f"(v.x), "f"(v.y), "f"(v.z), "f"(v.w) : "memory");
}
__device__ __forceinline__ float4 ldcs4(const float* p) {
    float4 v;
    asm volatile("ld.global.cs.v4.f32 {%0,%1,%2,%3}, [%4];"
                 : "=f"(v.x), "=f"(v.y), "=f"(v.z), "=f"(v.w) : "l"(p));
    return v;
}
__device__ __forceinline__ float ldcs1(const float* p) {
    float v;
    asm volatile("ld.global.cs.f32 %0, [%1];" : "=f"(v) : "l"(p));
    return v;
}

// ---------------- CSR build ----------------
__global__ void hist_deg(const int* __restrict__ ei, int E, int* __restrict__ deg) {
    int e = blockIdx.x * blockDim.x + threadIdx.x;
    if (e < E) atomicAdd(&deg[ei[E + e]], 1);
}

__global__ void scan_excl(const int* __restrict__ deg, int* __restrict__ ptr,
                          int* __restrict__ next, int n) {
    __shared__ int part[1024];
    const int tid = threadIdx.x;
    const int seg = (n + 1023) / 1024;
    const int lo = tid * seg;
    const int hi = min(n, lo + seg);
    int s = 0;
    for (int i = lo; i < hi; i++) s += deg[i];
    part[tid] = s;
    __syncthreads();
    if (tid == 0) {
        int run = 0;
        for (int i = 0; i < 1024; i++) { int v = part[i]; part[i] = run; run += v; }
    }
    __syncthreads();
    int run = part[tid];
    for (int i = lo; i < hi; i++) {
        ptr[i] = run;
        next[i] = run;
        run += deg[i];
    }
    if (hi == n && lo <= n) ptr[n] = run;
}

__global__ void fill_csr(const int* __restrict__ ei, int E,
                         int* __restrict__ next, int* __restrict__ col) {
    int e = blockIdx.x * blockDim.x + threadIdx.x;
    if (e >= E) return;
    int s = ei[e];
    int d = ei[E + e];
    int pos = atomicAdd(&next[d], 1);
    col[pos] = s;
}

// ---------------- gather-aggregate: warp per dst, 4-way MLP, streaming agg writes ----
__global__ __launch_bounds__(256) void gather_mean(
    const float* __restrict__ src, const int* __restrict__ ptr,
    const int* __restrict__ col, int n, float* __restrict__ agg)
{
    const int w = (blockIdx.x * blockDim.x + threadIdx.x) >> 5;
    if (w >= n) return;
    const int lane = threadIdx.x & 31;
    const int s0 = __ldg(&ptr[w]);
    const int s1 = __ldg(&ptr[w + 1]);
    float4 a0 = make_float4(0.f, 0.f, 0.f, 0.f);
    float4 a1 = make_float4(0.f, 0.f, 0.f, 0.f);
    float4 a2 = make_float4(0.f, 0.f, 0.f, 0.f);
    float4 a3 = make_float4(0.f, 0.f, 0.f, 0.f);
    int e = s0;
    for (; e + 3 < s1; e += 4) {
        int iA = __ldg(&col[e]);
        int iB = __ldg(&col[e + 1]);
        int iC = __ldg(&col[e + 2]);
        int iD = __ldg(&col[e + 3]);
        float4 vA = *(const float4*)(src + (size_t)iA * HDIM + lane * 4);
        float4 vB = *(const float4*)(src + (size_t)iB * HDIM + lane * 4);
        float4 vC = *(const float4*)(src + (size_t)iC * HDIM + lane * 4);
        float4 vD = *(const float4*)(src + (size_t)iD * HDIM + lane * 4);
        a0.x += vA.x; a0.y += vA.y; a0.z += vA.z; a0.w += vA.w;
        a1.x += vB.x; a1.y += vB.y; a1.z += vB.z; a1.w += vB.w;
        a2.x += vC.x; a2.y += vC.y; a2.z += vC.z; a2.w += vC.w;
        a3.x += vD.x; a3.y += vD.y; a3.z += vD.z; a3.w += vD.w;
    }
    for (; e < s1; e++) {
        int iA = __ldg(&col[e]);
        float4 vA = *(const float4*)(src + (size_t)iA * HDIM + lane * 4);
        a0.x += vA.x; a0.y += vA.y; a0.z += vA.z; a0.w += vA.w;
    }
    float inv = 1.0f / (float)max(s1 - s0, 1);
    float4 r;
    r.x = (a0.x + a1.x + a2.x + a3.x) * inv;
    r.y = (a0.y + a1.y + a2.y + a3.y) * inv;
    r.z = (a0.z + a1.z + a2.z + a3.z) * inv;
    r.w = (a0.w + a1.w + a2.w + a3.w) * inv;
    stcs4(agg + (size_t)w * HDIM + lane * 4, r);   // streaming: don't pollute L2
}

// ---------------- weights ----------------
__global__ void prep_weights(const float* __restrict__ Wl, const float* __restrict__ Wr,
                             float* __restrict__ Bt) {
    int i = blockIdx.x * blockDim.x + threadIdx.x;
    const int total = 2 * 2 * 128 * 384;
    if (i >= total) return;
    int k = i % 384;
    int n = (i / 384) & 127;
    int t = (i / (384 * 128)) & 1;
    int b = i / (384 * 128 * 2);
    int ta = t ? 1 : 0, tb = t ? 3 : 2;
    int seg = k >> 7, kk = k & 127;
    float v;
    if (seg == 0)      v = Wl[(((size_t)b * 4 + ta) * 128 + n) * 128 + kk];
    else if (seg == 1) v = Wl[(((size_t)b * 4 + tb) * 128 + n) * 128 + kk];
    else               v = Wr[(((size_t)b * 4 + ta) * 128 + n) * 128 + kk]
                         + Wr[(((size_t)b * 4 + tb) * 128 + n) * 128 + kk];
    Bt[i] = 0.5f * v;
}

// ---------------- WMMA tf32 GEMM ----------------
__global__ __launch_bounds__(256) void gemm_wmma(
    const float* __restrict__ A0, const float* __restrict__ A1, const float* __restrict__ A2,
    const float* __restrict__ Bt, float* __restrict__ out, int nrows)
{
    __shared__ float Bs[128 * 36];
    const int tid = threadIdx.x;
    const int wid = tid >> 5;
    const int wrow = blockIdx.x * 128 + wid * 16;
    const bool wvalid = wrow < nrows;

    wmma::fragment<wmma::accumulator, 16, 16, 8, float> acc[8];
#pragma unroll
    for (int nt = 0; nt < 8; nt++) wmma::fill_fragment(acc[nt], 0.0f);

    for (int chunk = 0; chunk < 12; chunk++) {
        const float* Asrc = (chunk < 4) ? A0 : (chunk < 8) ? A1 : A2;
        const int kbase = chunk * 32;
        const int koff = (chunk & 3) * 32;

#pragma unroll
        for (int i = 0; i < 4; i++) {
            int idx = tid + i * 256;
            int n = idx >> 3, q = idx & 7;
            *(float4*)&Bs[n * 36 + q * 4] =
                *(const float4*)(Bt + (size_t)n * 384 + kbase + q * 4);
        }
        __syncthreads();

        if (wvalid) {
#pragma unroll
            for (int kk = 0; kk < 4; kk++) {
                wmma::fragment<wmma::matrix_a, 16, 16, 8, wmma::precision::tf32,
                               wmma::row_major> a;
                wmma::load_matrix_sync(a, Asrc + (size_t)wrow * HDIM + koff + kk * 8, HDIM);
#pragma unroll
                for (int t = 0; t < a.num_elements; t++)
                    a.x[t] = wmma::__float_to_tf32(a.x[t]);
#pragma unroll
                for (int nt = 0; nt < 8; nt++) {
                    wmma::fragment<wmma::matrix_b, 16, 16, 8, wmma::precision::tf32,
                                   wmma::col_major> b;
                    wmma::load_matrix_sync(b, Bs + nt * 16 * 36 + kk * 8, 36);
#pragma unroll
                    for (int t = 0; t < b.num_elements; t++)
                        b.x[t] = wmma::__float_to_tf32(b.x[t]);
                    wmma::mma_sync(acc[nt], a, b, acc[nt]);
                }
            }
        }
        __syncthreads();
    }

    if (wvalid) {
#pragma unroll
        for (int nt = 0; nt < 8; nt++)
            wmma::store_matrix_sync(out + (size_t)wrow * HDIM + nt * 16, acc[nt],
                                    HDIM, wmma::mem_row_major);
    }
}

// ---------------- BN + LeakyReLU ----------------
__global__ void bn_stats(const float* __restrict__ v, int n,
                         float* __restrict__ sum, float* __restrict__ sq) {
    int c = threadIdx.x & 127;
    int sub = threadIdx.x >> 7;
    float s = 0.f, s2 = 0.f;
    for (int r = blockIdx.x * 2 + sub; r < n; r += gridDim.x * 2) {
        float x = ldcs1(v + (size_t)r * HDIM + c);   // single-use stream
        s += x;
        s2 += x * x;
    }
    __shared__ float sh[256], sh2[256];
    sh[threadIdx.x] = s;
    sh2[threadIdx.x] = s2;
    __syncthreads();
    if (sub == 0) {
        atomicAdd(&sum[c], sh[c] + sh[c + 128]);
        atomicAdd(&sq[c], sh2[c] + sh2[c + 128]);
    }
}

// in (GEMM output) read streaming; out (next hot table) written with default policy.
__global__ void bn_apply(const float* __restrict__ in, float* __restrict__ out, int n,
                         const float* __restrict__ sum, const float* __restrict__ sq,
                         const float* __restrict__ gamma, const float* __restrict__ beta) {
    size_t i4 = (size_t)blockIdx.x * blockDim.x + threadIdx.x;   // float4 index
    size_t total4 = (size_t)n * (HDIM / 4);
    if (i4 >= total4) return;
    int c4 = (int)(i4 & 31);             // float4 lane within row
    float N = (float)n;
    float4 v = ldcs4(in + i4 * 4);
    float o[4];
#pragma unroll
    for (int j = 0; j < 4; j++) {
        int c = c4 * 4 + j;
        float mu = sum[c] / N;
        float var = sq[c] / N - mu * mu;
        float rstd = rsqrtf(var + 1e-5f);
        float x = (((&v.x)[j]) - mu) * rstd * gamma[c] + beta[c];
        o[j] = x >= 0.f ? x : 0.01f * x;
    }
    *(float4*)(out + i4 * 4) = make_float4(o[0], o[1], o[2], o[3]);
}

// ---------------- host ----------------
static inline void* sym(const void* s) {
    void* p = 0;
    cudaGetSymbolAddress(&p, s);
    return p;
}

extern "C" void kernel_launch(void* const* d_in, const int* in_sizes, int n_in,
                              void* d_out, int out_size) {
    const float* x_host = (const float*)d_in[0];
    const float* x_flow = (const float*)d_in[1];
    const int* ei_sends = (const int*)d_in[2];
    const int* ei_rev   = (const int*)d_in[3];
    const int* ei_prec  = (const int*)d_in[4];
    const int* ei_reach = (const int*)d_in[5];
    const float* W_l = (const float*)d_in[6];
    const float* W_r = (const float*)d_in[8];
    const float* bn_gamma = (const float*)d_in[9];
    const float* bn_beta  = (const float*)d_in[10];
    float* out = (float*)d_out;

    int E_sends = in_sizes[2] / 2;
    int E_rev   = in_sizes[3] / 2;
    int E_prec  = in_sizes[4] / 2;
    int E_reach = in_sizes[5] / 2;

    float* agg_f0 = (float*)sym(g_agg_f0);
    float* agg_f1 = (float*)sym(g_agg_f1);
    float* agg_h0 = (float*)sym(g_agg_h0);
    float* agg_h1 = (float*)sym(g_agg_h1);
    float* f_buf1 = (float*)sym(g_f_buf1);
    float* f_buf2 = (float*)sym(g_f_buf2);
    float* h_buf1 = (float*)sym(g_h_buf1);
    float* h_buf2 = (float*)sym(g_h_buf2);
    float* Bt    = (float*)sym(g_Bt);
    float* stats = (float*)sym(g_stats);

    int* deg       = (int*)sym(g_deg);
    int* ptr_sends = (int*)sym(g_ptr_sends);
    int* ptr_prec  = (int*)sym(g_ptr_prec);
    int* ptr_rev   = (int*)sym(g_ptr_rev);
    int* ptr_reach = (int*)sym(g_ptr_reach);
    int* nxt       = (int*)sym(g_next);
    int* col_sends = (int*)sym(g_col_sends);
    int* col_prec  = (int*)sym(g_col_prec);
    int* col_rev   = (int*)sym(g_col_rev);
    int* col_reach = (int*)sym(g_col_reach);

    // ---- CSR build (once) ----
    struct { const int* ei; int E; int n; int* ptr; int* col; } T[4] = {
        { ei_sends, E_sends, NF, ptr_sends, col_sends },
        { ei_prec,  E_prec,  NF, ptr_prec,  col_prec  },
        { ei_rev,   E_rev,   NH, ptr_rev,   col_rev   },
        { ei_reach, E_reach, NH, ptr_reach, col_reach },
    };
    for (int t = 0; t < 4; t++) {
        cudaMemsetAsync(deg, 0, (size_t)T[t].n * sizeof(int));
        hist_deg<<<(T[t].E + 255) / 256, 256>>>(T[t].ei, T[t].E, deg);
        scan_excl<<<1, 1024>>>(deg, T[t].ptr, nxt, T[t].n);
        fill_csr<<<(T[t].E + 255) / 256, 256>>>(T[t].ei, T[t].E, nxt, T[t].col);
    }

    // ---- fused weights ----
    {
        int tot = 2 * 2 * 128 * 384;
        prep_weights<<<(tot + 255) / 256, 256>>>(W_l, W_r, Bt);
    }

    const int gemm_grid_f = (NF + 127) / 128;
    const int gemm_grid_h = (NH + 127) / 128;
    const int gat_grid_f = (NF * 32 + 255) / 256;
    const int gat_grid_h = (NH * 32 + 255) / 256;

    const float* h_cur = x_host;
    const float* f_cur = x_flow;

    for (int blk = 0; blk < NUM_BLOCKS; blk++) {
        float* f_next = blk == 0 ? f_buf1 : f_buf2;
        float* h_next = blk == 0 ? h_buf1 : h_buf2;

        gather_mean<<<gat_grid_f, 256>>>(h_cur, ptr_sends, col_sends, NF, agg_f0);
        gather_mean<<<gat_grid_f, 256>>>(f_cur, ptr_prec, col_prec, NF, agg_f1);
        gather_mean<<<gat_grid_h, 256>>>(f_cur, ptr_rev, col_rev, NH, agg_h0);
        gather_mean<<<gat_grid_h, 256>>>(f_cur, ptr_reach, col_reach, NH, agg_h1);

        const float* Bf = Bt + (size_t)(blk * 2 + 0) * 128 * 384;
        const float* Bh = Bt + (size_t)(blk * 2 + 1) * 128 * 384;
        gemm_wmma<<<gemm_grid_f, 256>>>(agg_f0, agg_f1, f_cur, Bf, f_next, NF);
        gemm_wmma<<<gemm_grid_h, 256>>>(agg_h0, agg_h1, h_cur, Bh, h_next, NH);

        cudaMemsetAsync(stats, 0, 4 * HDIM * 4);
        bn_stats<<<1024, 256>>>(h_next, NH, stats, stats + HDIM);
        bn_stats<<<1024, 256>>>(f_next, NF, stats + 2 * HDIM, stats + 3 * HDIM);

        const float* gamma = bn_gamma + blk * HDIM;
        const float* beta  = bn_beta + blk * HDIM;
        float* h_out = (blk == NUM_BLOCKS - 1) ? out : h_next;
        float* f_out = (blk == NUM_BLOCKS - 1) ? (out + (size_t)NH * HDIM) : f_next;
        {
            size_t tot4 = (size_t)NH * (HDIM / 4);
            bn_apply<<<(int)((tot4 + 255) / 256), 256>>>(h_next, h_out, NH, stats,
                                                         stats + HDIM, gamma, beta);
        }
        {
            size_t tot4 = (size_t)NF * (HDIM / 4);
            bn_apply<<<(int)((tot4 + 255) / 256), 256>>>(f_next, f_out, NF, stats + 2 * HDIM,
                                                         stats + 3 * HDIM, gamma, beta);
        }

        h_cur = h_next;
        f_cur = f_next;
    }
}